// round 4
// baseline (speedup 1.0000x reference)
#include <cuda_runtime.h>
#include <cuda_bf16.h>
#include <cstdint>
#include <cstddef>

// ---------------------------------------------------------------------------
// Problem dims
// ---------------------------------------------------------------------------
#define B_DIM   128
#define L_DIM   512
#define IN_DIM  512
#define MEM     1024
#define NOUT    2048
#define M_DIM   (B_DIM * L_DIM)      // 65536

#define NCHUNK  24                   // K' = 1536 = 24 * 64
#define KC      64

// ---------------------------------------------------------------------------
// Device scratch (static allocation — no runtime alloc)
// g_A2: [mt(512)][chunk(16)][128 rows][64 cols] bf16, SW128-swizzled 16KB blocks
//        chunks 0-7 = hi, 8-15 = lo
// g_W2: [wt(16)][chunk(16)][128 rows][64 cols] bf16, same layout
// ---------------------------------------------------------------------------
__device__ float          g_emb[(size_t)M_DIM * NOUT];          // 512 MB
__device__ __nv_bfloat16  g_A2[(size_t)M_DIM * 1024];           // 128 MB
__device__ __nv_bfloat16  g_W2[(size_t)NOUT * 1024];            // 4 MB

// ---------------------------------------------------------------------------
// Helpers
// ---------------------------------------------------------------------------
__device__ __forceinline__ uint32_t smem_u32(const void* p) {
    uint32_t a;
    asm("{ .reg .u64 t; cvta.to.shared.u64 t, %1; cvt.u32.u64 %0, t; }" : "=r"(a) : "l"(p));
    return a;
}
__device__ __forceinline__ uint32_t swz(uint32_t b) { return b ^ ((b >> 3) & 0x70); }

__device__ __forceinline__ void cp_async16(uint32_t dst, const void* src) {
    asm volatile("cp.async.cg.shared.global [%0], [%1], 16;" :: "r"(dst), "l"(src) : "memory");
}
__device__ __forceinline__ void cp_commit() {
    asm volatile("cp.async.commit_group;" ::: "memory");
}
template <int N>
__device__ __forceinline__ void cp_wait() {
    asm volatile("cp.async.wait_group %0;" :: "n"(N) : "memory");
}

#define LDSM4(r0, r1, r2, r3, a) \
    asm volatile("ldmatrix.sync.aligned.m8n8.x4.shared.b16 {%0,%1,%2,%3}, [%4];" \
                 : "=r"(r0), "=r"(r1), "=r"(r2), "=r"(r3) : "r"(a))

#define MMA16816(c0, c1, c2, c3, a0, a1, a2, a3, b0, b1) \
    asm volatile("mma.sync.aligned.m16n8k16.row.col.f32.bf16.bf16.f32 " \
                 "{%0,%1,%2,%3}, {%4,%5,%6,%7}, {%8,%9}, {%0,%1,%2,%3};" \
                 : "+f"(c0), "+f"(c1), "+f"(c2), "+f"(c3) \
                 : "r"(a0), "r"(a1), "r"(a2), "r"(a3), "r"(b0), "r"(b1))

// fast tanh (error ~1e-6, correctness threshold is 1e-3)
__device__ __forceinline__ float tanh_fast(float x) {
    float a = fabsf(x);
    float e = __expf(-2.0f * a);
    float r = __fdividef(1.0f - e, 1.0f + e);
    return copysignf(r, x);
}

// ---------------------------------------------------------------------------
// Conversion kernels: fp32 -> bf16 hi/lo, tiled + SW128 pre-swizzled blocks
// ---------------------------------------------------------------------------
__global__ __launch_bounds__(256) void conv_a_kernel(const float* __restrict__ u) {
    int idx = blockIdx.x * 256 + threadIdx.x;
    int m = idx >> 8;
    int k = (idx & 255) * 2;
    float2 v = *(const float2*)(u + (size_t)m * IN_DIM + k);
    __nv_bfloat16 h0 = __float2bfloat16(v.x);
    __nv_bfloat16 h1 = __float2bfloat16(v.y);
    __nv_bfloat16 l0 = __float2bfloat16(v.x - __bfloat162float(h0));
    __nv_bfloat16 l1 = __float2bfloat16(v.y - __bfloat162float(h1));
    uint32_t hp = (uint32_t)*(unsigned short*)&h0 | ((uint32_t)*(unsigned short*)&h1 << 16);
    uint32_t lp = (uint32_t)*(unsigned short*)&l0 | ((uint32_t)*(unsigned short*)&l1 << 16);
    int mt = m >> 7, r = m & 127;
    int ch = k >> 6, c = k & 63;
    uint32_t off = swz((uint32_t)(r * 128 + c * 2));
    char* base = (char*)g_A2;
    *(uint32_t*)(base + (((size_t)(mt * 16 + ch))     << 14) + off) = hp;
    *(uint32_t*)(base + (((size_t)(mt * 16 + 8 + ch)) << 14) + off) = lp;
}

__global__ __launch_bounds__(256) void conv_w_kernel(const float* __restrict__ W) {
    int idx = blockIdx.x * 256 + threadIdx.x;
    int n = idx >> 8;
    int k = (idx & 255) * 2;
    float2 v = *(const float2*)(W + (size_t)n * IN_DIM + k);
    __nv_bfloat16 h0 = __float2bfloat16(v.x);
    __nv_bfloat16 h1 = __float2bfloat16(v.y);
    __nv_bfloat16 l0 = __float2bfloat16(v.x - __bfloat162float(h0));
    __nv_bfloat16 l1 = __float2bfloat16(v.y - __bfloat162float(h1));
    uint32_t hp = (uint32_t)*(unsigned short*)&h0 | ((uint32_t)*(unsigned short*)&h1 << 16);
    uint32_t lp = (uint32_t)*(unsigned short*)&l0 | ((uint32_t)*(unsigned short*)&l1 << 16);
    int nt = n >> 7, r = n & 127;
    int ch = k >> 6, c = k & 63;
    uint32_t off = swz((uint32_t)(r * 128 + c * 2));
    char* base = (char*)g_W2;
    *(uint32_t*)(base + (((size_t)(nt * 16 + ch))     << 14) + off) = hp;
    *(uint32_t*)(base + (((size_t)(nt * 16 + 8 + ch)) << 14) + off) = lp;
}

// ---------------------------------------------------------------------------
// bf16 warp-MMA GEMM: C[m][n] = sum_{k'=0..1535} A''[m][k'] * W''[n][k']
// CTA tile 128x256, BK=64, 256 threads (8 warps, 2(m) x 4(n), warp tile 64x64).
// 3-stage cp.async pipeline, 144 KB smem, 1 CTA/SM. Grid (8, 512).
// ---------------------------------------------------------------------------
#define NST 3
#define STAGE_BYTES 49152                     // A 16KB + B 32KB
#define SMEM_TOTAL (NST * STAGE_BYTES)        // 144 KB

__global__ __launch_bounds__(256, 1) void gemm_mma_kernel(const float* __restrict__ bias) {
    extern __shared__ __align__(1024) char smem[];
    const uint32_t sm   = smem_u32(smem);
    const int tid  = threadIdx.x;
    const int wid  = tid >> 5;
    const int lane = tid & 31;
    const int nt   = blockIdx.x;     // 0..7   (N-tile of 256)
    const int mt   = blockIdx.y;     // 0..511
    const int wm   = wid >> 2;       // 0..1
    const int wn   = wid & 3;        // 0..3

    const char* Ab = (const char*)g_A2 + ((size_t)mt << 18);          // mt * 16 * 16KB
    const char* B0 = (const char*)g_W2 + ((size_t)(2 * nt) << 18);    // wt = 2nt
    const char* B1 = (const char*)g_W2 + ((size_t)(2 * nt + 1) << 18);

    float acc[4][8][4];
#pragma unroll
    for (int i = 0; i < 4; i++)
#pragma unroll
        for (int j = 0; j < 8; j++)
#pragma unroll
            for (int e = 0; e < 4; e++) acc[i][j][e] = 0.0f;

    // ldmatrix per-lane addressing (SW128): phys = row*128 + ((c16 ^ (row&7))*16)
    const int jj = lane >> 3;        // matrix index 0..3
    const int rl = lane & 7;
    uint32_t arow[4], brow[4];
#pragma unroll
    for (int mi = 0; mi < 4; mi++)
        arow[mi] = (uint32_t)((wm * 64 + mi * 16 + (jj & 1) * 8 + rl) * 128);
#pragma unroll
    for (int p = 0; p < 4; p++) {
        int nrow = wn * 64 + p * 16 + (jj & 1) * 8 + rl;      // 0..255
        brow[p] = (uint32_t)((nrow >= 128) ? (16384 + (nrow - 128) * 128) : (nrow * 128));
    }

    auto load_stage = [&](int c, int s) {
        int ach = (c >= 16) ? (8 + c - 16) : (c & 7);   // A: [hi x8 | hi x8 | lo x8]
        int wch = (c >= 16) ? (c - 16)     : c;          // W: [hi x8 | lo x8 | hi x8]
        const char* As  = Ab + ((size_t)ach << 14);
        const char* Bs0 = B0 + ((size_t)wch << 14);
        const char* Bs1 = B1 + ((size_t)wch << 14);
        uint32_t dst = sm + (uint32_t)s * STAGE_BYTES;
#pragma unroll
        for (int i = 0; i < 4; i++) {
            uint32_t off = (uint32_t)(tid + i * 256) * 16;
            cp_async16(dst + off, As + off);
        }
#pragma unroll
        for (int i = 0; i < 4; i++) {
            uint32_t off = (uint32_t)(tid + i * 256) * 16;
            cp_async16(dst + 16384 + off, Bs0 + off);
        }
#pragma unroll
        for (int i = 0; i < 4; i++) {
            uint32_t off = (uint32_t)(tid + i * 256) * 16;
            cp_async16(dst + 32768 + off, Bs1 + off);
        }
        cp_commit();
    };

    load_stage(0, 0);
    load_stage(1, 1);

    for (int ck = 0; ck < NCHUNK; ck++) {
        const int s = ck % NST;
        cp_wait<1>();
        __syncthreads();
        if (ck + 2 < NCHUNK) load_stage(ck + 2, (ck + 2) % NST);

        const uint32_t sA = sm + (uint32_t)s * STAGE_BYTES;
        const uint32_t sB = sA + 16384;

#pragma unroll
        for (int ks = 0; ks < 4; ks++) {
            const uint32_t cb = (uint32_t)(((2 * ks + (jj >> 1)) ^ rl) * 16);
            uint32_t a[4][4], br[4][4];
#pragma unroll
            for (int mi = 0; mi < 4; mi++)
                LDSM4(a[mi][0], a[mi][1], a[mi][2], a[mi][3], sA + arow[mi] + cb);
#pragma unroll
            for (int p = 0; p < 4; p++)
                LDSM4(br[p][0], br[p][1], br[p][2], br[p][3], sB + brow[p] + cb);
#pragma unroll
            for (int mi = 0; mi < 4; mi++) {
#pragma unroll
                for (int ni = 0; ni < 8; ni++) {
                    const int p = ni >> 1, sub = ni & 1;
                    MMA16816(acc[mi][ni][0], acc[mi][ni][1], acc[mi][ni][2], acc[mi][ni][3],
                             a[mi][0], a[mi][1], a[mi][2], a[mi][3],
                             br[p][sub], br[p][sub + 2]);
                }
            }
        }
    }

    // Epilogue: bias + soma-bias transform on first 1024 cols, streamed fp32 stores
    const int  n0    = nt * 256;
    const bool is_sb = (nt < 4);
#pragma unroll
    for (int mi = 0; mi < 4; mi++) {
        const int row0 = mt * 128 + wm * 64 + mi * 16 + (lane >> 2);
#pragma unroll
        for (int ni = 0; ni < 8; ni++) {
            const int col = n0 + wn * 64 + ni * 8 + (lane & 3) * 2;
            const float2 b2 = *(const float2*)(bias + col);
            float v0 = acc[mi][ni][0] + b2.x;
            float v1 = acc[mi][ni][1] + b2.y;
            float v2 = acc[mi][ni][2] + b2.x;
            float v3 = acc[mi][ni][3] + b2.y;
            if (is_sb) {
                v0 = 5.0f * tanh_fast(v0 * 0.2f);
                v1 = 5.0f * tanh_fast(v1 * 0.2f);
                v2 = 5.0f * tanh_fast(v2 * 0.2f);
                v3 = 5.0f * tanh_fast(v3 * 0.2f);
            }
            __stcs((float2*)&g_emb[(size_t)row0 * NOUT + col],       make_float2(v0, v1));
            __stcs((float2*)&g_emb[(size_t)(row0 + 8) * NOUT + col], make_float2(v2, v3));
        }
    }
}

// ---------------------------------------------------------------------------
// Phase 2: sequential scan over L. One thread per (b, mem) lane.
// Group-of-4 software prefetch (8 loads in flight), streaming cache hints.
// out layout: h_t [B][L][MEM] ++ hf_last [B][MEM]
// ---------------------------------------------------------------------------
__global__ __launch_bounds__(256) void scan_kernel(const float* __restrict__ h0,
                                                   float* __restrict__ out)
{
    const int idx = blockIdx.x * 256 + threadIdx.x;
    const int b   = idx >> 10;

    float hf = h0[idx];
    float hs = h0[B_DIM * MEM + idx];

    const float* e = g_emb + (size_t)b * L_DIM * NOUT + (idx & (MEM - 1));
    float*       o = out   + (size_t)b * L_DIM * MEM  + (idx & (MEM - 1));

    float psb[4], pio[4];
#pragma unroll
    for (int j = 0; j < 4; j++) {
        psb[j] = __ldcs(e + (size_t)j * NOUT);
        pio[j] = __ldcs(e + (size_t)j * NOUT + MEM);
    }

    for (int g = 0; g < L_DIM / 4; g++) {
        float csb[4], cio[4];
#pragma unroll
        for (int j = 0; j < 4; j++) { csb[j] = psb[j]; cio[j] = pio[j]; }
        if (g + 1 < L_DIM / 4) {
            const float* en = e + (size_t)(g + 1) * 4 * NOUT;
#pragma unroll
            for (int j = 0; j < 4; j++) {
                psb[j] = __ldcs(en + (size_t)j * NOUT);
                pio[j] = __ldcs(en + (size_t)j * NOUT + MEM);
            }
        }
#pragma unroll
        for (int j = 0; j < 4; j++) {
            const float hsb = hs + 0.4f;
            const float x   = cio[j] + 4.0f * hf - 7.0f * hsb * hsb + csb[j];
            const float hfn = tanh_fast(x);
            const float z   = (hf - 0.5f) * 10.0f;
            const float sig = __fdividef(1.0f, 1.0f + __expf(-z));
            const float eps = 0.9f + 0.9f * sig;
            const float hsn = (1.0f - eps) * hs + eps * hf;
            __stcs(o + (size_t)(g * 4 + j) * MEM, hfn);
            hf = hfn;
            hs = hsn;
        }
    }
    out[(size_t)M_DIM * MEM + idx] = hf;
}

// ---------------------------------------------------------------------------
// Launch
// ---------------------------------------------------------------------------
extern "C" void kernel_launch(void* const* d_in, const int* in_sizes, int n_in,
                              void* d_out, int out_size)
{
    const float* u    = (const float*)d_in[0];   // (128, 512, 512)
    const float* h0   = (const float*)d_in[1];   // (2, 128, 1024)
    const float* W    = (const float*)d_in[2];   // (2048, 512)
    const float* bias = (const float*)d_in[3];   // (2048,)
    float* out = (float*)d_out;

    cudaFuncSetAttribute(gemm_mma_kernel, cudaFuncAttributeMaxDynamicSharedMemorySize, SMEM_TOTAL);

    conv_a_kernel<<<(M_DIM * IN_DIM / 2) / 256, 256>>>(u);   // 65536 blocks
    conv_w_kernel<<<(NOUT * IN_DIM / 2) / 256, 256>>>(W);    // 2048 blocks

    dim3 grid(8, 512);
    gemm_mma_kernel<<<grid, 256, SMEM_TOTAL>>>(bias);

    scan_kernel<<<(B_DIM * MEM) / 256, 256>>>(h0, out);
}

// round 5
// speedup vs baseline: 1.5657x; 1.5657x over previous
#include <cuda_runtime.h>
#include <cuda_bf16.h>
#include <cstdint>
#include <cstddef>

// ---------------------------------------------------------------------------
// Problem dims
// ---------------------------------------------------------------------------
#define B_DIM   128
#define L_DIM   512
#define IN_DIM  512
#define MEM     1024
#define NOUT    2048
#define M_DIM   (B_DIM * L_DIM)      // 65536

#define NCHUNK  24                   // K' = 1536 = 24 * 64

// ---------------------------------------------------------------------------
// Device scratch (static allocation — no runtime alloc)
// g_A2: [mt(512)][chunk(16)][128 rows][64 cols] bf16, SW128-swizzled 16KB blocks
//        chunks 0-7 = hi, 8-15 = lo
// g_W2: [wt(16)][chunk(16)][128 rows][64 cols] bf16, same layout
// ---------------------------------------------------------------------------
__device__ float          g_emb[(size_t)M_DIM * NOUT];          // 512 MB
__device__ __nv_bfloat16  g_A2[(size_t)M_DIM * 1024];           // 128 MB
__device__ __nv_bfloat16  g_W2[(size_t)NOUT * 1024];            // 4 MB

// ---------------------------------------------------------------------------
// Helpers
// ---------------------------------------------------------------------------
__device__ __forceinline__ uint32_t smem_u32(const void* p) {
    uint32_t a;
    asm("{ .reg .u64 t; cvta.to.shared.u64 t, %1; cvt.u32.u64 %0, t; }" : "=r"(a) : "l"(p));
    return a;
}
__device__ __forceinline__ uint32_t swz(uint32_t b) { return b ^ ((b >> 3) & 0x70); }

__device__ __forceinline__ void cp_async16(uint32_t dst, const void* src) {
    asm volatile("cp.async.cg.shared.global [%0], [%1], 16;" :: "r"(dst), "l"(src) : "memory");
}
__device__ __forceinline__ void cp_commit() {
    asm volatile("cp.async.commit_group;" ::: "memory");
}
template <int N>
__device__ __forceinline__ void cp_wait() {
    asm volatile("cp.async.wait_group %0;" :: "n"(N) : "memory");
}

#define LDSM4(r0, r1, r2, r3, a) \
    asm volatile("ldmatrix.sync.aligned.m8n8.x4.shared.b16 {%0,%1,%2,%3}, [%4];" \
                 : "=r"(r0), "=r"(r1), "=r"(r2), "=r"(r3) : "r"(a))

#define MMA16816(c0, c1, c2, c3, a0, a1, a2, a3, b0, b1) \
    asm volatile("mma.sync.aligned.m16n8k16.row.col.f32.bf16.bf16.f32 " \
                 "{%0,%1,%2,%3}, {%4,%5,%6,%7}, {%8,%9}, {%0,%1,%2,%3};" \
                 : "+f"(c0), "+f"(c1), "+f"(c2), "+f"(c3) \
                 : "r"(a0), "r"(a1), "r"(a2), "r"(a3), "r"(b0), "r"(b1))

// fast tanh (error ~1e-6, correctness threshold is 1e-3)
__device__ __forceinline__ float tanh_fast(float x) {
    float a = fabsf(x);
    float e = __expf(-2.0f * a);
    float r = __fdividef(1.0f - e, 1.0f + e);
    return copysignf(r, x);
}

// ---------------------------------------------------------------------------
// Conversion kernels: fp32 -> bf16 hi/lo, tiled + SW128 pre-swizzled blocks
// ---------------------------------------------------------------------------
__global__ __launch_bounds__(256) void conv_a_kernel(const float* __restrict__ u) {
    int idx = blockIdx.x * 256 + threadIdx.x;
    int m = idx >> 8;
    int k = (idx & 255) * 2;
    float2 v = *(const float2*)(u + (size_t)m * IN_DIM + k);
    __nv_bfloat16 h0 = __float2bfloat16(v.x);
    __nv_bfloat16 h1 = __float2bfloat16(v.y);
    __nv_bfloat16 l0 = __float2bfloat16(v.x - __bfloat162float(h0));
    __nv_bfloat16 l1 = __float2bfloat16(v.y - __bfloat162float(h1));
    uint32_t hp = (uint32_t)*(unsigned short*)&h0 | ((uint32_t)*(unsigned short*)&h1 << 16);
    uint32_t lp = (uint32_t)*(unsigned short*)&l0 | ((uint32_t)*(unsigned short*)&l1 << 16);
    int mt = m >> 7, r = m & 127;
    int ch = k >> 6, c = k & 63;
    uint32_t off = swz((uint32_t)(r * 128 + c * 2));
    char* base = (char*)g_A2;
    *(uint32_t*)(base + (((size_t)(mt * 16 + ch))     << 14) + off) = hp;
    *(uint32_t*)(base + (((size_t)(mt * 16 + 8 + ch)) << 14) + off) = lp;
}

__global__ __launch_bounds__(256) void conv_w_kernel(const float* __restrict__ W) {
    int idx = blockIdx.x * 256 + threadIdx.x;
    int n = idx >> 8;
    int k = (idx & 255) * 2;
    float2 v = *(const float2*)(W + (size_t)n * IN_DIM + k);
    __nv_bfloat16 h0 = __float2bfloat16(v.x);
    __nv_bfloat16 h1 = __float2bfloat16(v.y);
    __nv_bfloat16 l0 = __float2bfloat16(v.x - __bfloat162float(h0));
    __nv_bfloat16 l1 = __float2bfloat16(v.y - __bfloat162float(h1));
    uint32_t hp = (uint32_t)*(unsigned short*)&h0 | ((uint32_t)*(unsigned short*)&h1 << 16);
    uint32_t lp = (uint32_t)*(unsigned short*)&l0 | ((uint32_t)*(unsigned short*)&l1 << 16);
    int nt = n >> 7, r = n & 127;
    int ch = k >> 6, c = k & 63;
    uint32_t off = swz((uint32_t)(r * 128 + c * 2));
    char* base = (char*)g_W2;
    *(uint32_t*)(base + (((size_t)(nt * 16 + ch))     << 14) + off) = hp;
    *(uint32_t*)(base + (((size_t)(nt * 16 + 8 + ch)) << 14) + off) = lp;
}

// ---------------------------------------------------------------------------
// bf16 warp-MMA GEMM: C[m][n] = sum_{k'=0..1535} A''[m][k'] * W''[n][k']
// CTA tile 128x128, BK=64, 128 threads (4 warps, 2(m) x 2(n), warp tile 64x64).
// 3-stage cp.async pipeline, 96 KB smem, 2 CTAs/SM. Grid (16, 512).
// ---------------------------------------------------------------------------
#define NST 3
#define STAGE_BYTES 32768                     // A 16KB + B 16KB
#define SMEM_TOTAL (NST * STAGE_BYTES)        // 96 KB

__global__ __launch_bounds__(128, 2) void gemm_mma_kernel(const float* __restrict__ bias) {
    extern __shared__ __align__(1024) char smem[];
    const uint32_t sm   = smem_u32(smem);
    const int tid  = threadIdx.x;
    const int wid  = tid >> 5;
    const int lane = tid & 31;
    const int nt   = blockIdx.x;     // 0..15
    const int mt   = blockIdx.y;     // 0..511
    const int wm   = wid >> 1;       // 0..1
    const int wn   = wid & 1;        // 0..1

    const char* Ab = (const char*)g_A2 + ((size_t)mt << 18);   // mt * 16 blocks * 16KB
    const char* Bb = (const char*)g_W2 + ((size_t)nt << 18);

    float acc[4][8][4];
#pragma unroll
    for (int i = 0; i < 4; i++)
#pragma unroll
        for (int j = 0; j < 8; j++)
#pragma unroll
            for (int e = 0; e < 4; e++) acc[i][j][e] = 0.0f;

    // ldmatrix per-lane addressing (SW128): phys = row*128 + ((c16 ^ (row&7))*16)
    const int jj = lane >> 3;        // matrix index 0..3
    const int rl = lane & 7;
    uint32_t arow[4], brow[4];
#pragma unroll
    for (int mi = 0; mi < 4; mi++)
        arow[mi] = (uint32_t)((wm * 64 + mi * 16 + (jj & 1) * 8 + rl) * 128);
#pragma unroll
    for (int p = 0; p < 4; p++)
        brow[p] = (uint32_t)((wn * 64 + p * 16 + (jj & 1) * 8 + rl) * 128);

    auto load_stage = [&](int c, int s) {
        int ach = (c >= 16) ? (8 + c - 16) : (c & 7);   // A: [hi x8 | hi x8 | lo x8]
        int wch = (c >= 16) ? (c - 16)     : c;          // W: [hi x8 | lo x8 | hi x8]
        const char* As = Ab + ((size_t)ach << 14);
        const char* Bs = Bb + ((size_t)wch << 14);
        uint32_t dst = sm + (uint32_t)s * STAGE_BYTES;
#pragma unroll
        for (int i = 0; i < 8; i++) {
            uint32_t off = (uint32_t)(tid + i * 128) * 16;
            cp_async16(dst + off, As + off);
        }
#pragma unroll
        for (int i = 0; i < 8; i++) {
            uint32_t off = (uint32_t)(tid + i * 128) * 16;
            cp_async16(dst + 16384 + off, Bs + off);
        }
        cp_commit();
    };

    load_stage(0, 0);
    load_stage(1, 1);

    for (int ck = 0; ck < NCHUNK; ck++) {
        const int s = ck % NST;
        cp_wait<1>();
        __syncthreads();
        if (ck + 2 < NCHUNK) load_stage(ck + 2, (ck + 2) % NST);

        const uint32_t sA = sm + (uint32_t)s * STAGE_BYTES;
        const uint32_t sB = sA + 16384;

#pragma unroll
        for (int ks = 0; ks < 4; ks++) {
            const uint32_t cb = (uint32_t)(((2 * ks + (jj >> 1)) ^ rl) * 16);
            uint32_t a[4][4], br[4][4];
#pragma unroll
            for (int mi = 0; mi < 4; mi++)
                LDSM4(a[mi][0], a[mi][1], a[mi][2], a[mi][3], sA + arow[mi] + cb);
#pragma unroll
            for (int p = 0; p < 4; p++)
                LDSM4(br[p][0], br[p][1], br[p][2], br[p][3], sB + brow[p] + cb);
#pragma unroll
            for (int mi = 0; mi < 4; mi++) {
#pragma unroll
                for (int ni = 0; ni < 8; ni++) {
                    const int p = ni >> 1, sub = ni & 1;
                    MMA16816(acc[mi][ni][0], acc[mi][ni][1], acc[mi][ni][2], acc[mi][ni][3],
                             a[mi][0], a[mi][1], a[mi][2], a[mi][3],
                             br[p][sub], br[p][sub + 2]);
                }
            }
        }
    }

    // Epilogue: bias + soma-bias transform on first 1024 cols, streamed fp32 stores
    const int  n0    = nt * 128;
    const bool is_sb = (nt < 8);
#pragma unroll
    for (int mi = 0; mi < 4; mi++) {
        const int row0 = mt * 128 + wm * 64 + mi * 16 + (lane >> 2);
#pragma unroll
        for (int ni = 0; ni < 8; ni++) {
            const int col = n0 + wn * 64 + ni * 8 + (lane & 3) * 2;
            const float2 b2 = *(const float2*)(bias + col);
            float v0 = acc[mi][ni][0] + b2.x;
            float v1 = acc[mi][ni][1] + b2.y;
            float v2 = acc[mi][ni][2] + b2.x;
            float v3 = acc[mi][ni][3] + b2.y;
            if (is_sb) {
                v0 = 5.0f * tanh_fast(v0 * 0.2f);
                v1 = 5.0f * tanh_fast(v1 * 0.2f);
                v2 = 5.0f * tanh_fast(v2 * 0.2f);
                v3 = 5.0f * tanh_fast(v3 * 0.2f);
            }
            __stcs((float2*)&g_emb[(size_t)row0 * NOUT + col],       make_float2(v0, v1));
            __stcs((float2*)&g_emb[(size_t)(row0 + 8) * NOUT + col], make_float2(v2, v3));
        }
    }
}

// ---------------------------------------------------------------------------
// Phase 2: sequential scan over L. One thread per (b, mem) lane.
// (round-3 form — simple loop, ptxas hoists the loads)
// out layout: h_t [B][L][MEM] ++ hf_last [B][MEM]
// ---------------------------------------------------------------------------
__global__ __launch_bounds__(256) void scan_kernel(const float* __restrict__ h0,
                                                   float* __restrict__ out)
{
    const int idx = blockIdx.x * 256 + threadIdx.x;
    const int b   = idx >> 10;

    float hf = h0[idx];
    float hs = h0[B_DIM * MEM + idx];

    const float* e = g_emb + (size_t)b * L_DIM * NOUT + (idx & (MEM - 1));
    float*       o = out   + (size_t)b * L_DIM * MEM  + (idx & (MEM - 1));

#pragma unroll 4
    for (int l = 0; l < L_DIM; l++) {
        const float sb = e[(size_t)l * NOUT];
        const float io = e[(size_t)l * NOUT + MEM];

        const float hsb = hs + 0.4f;
        const float x   = io + 4.0f * hf - 7.0f * hsb * hsb + sb;
        const float hfn = tanh_fast(x);
        const float z   = (hf - 0.5f) * 10.0f;
        const float sig = __fdividef(1.0f, 1.0f + __expf(-z));
        const float eps = 0.9f + 0.9f * sig;
        const float hsn = (1.0f - eps) * hs + eps * hf;

        o[(size_t)l * MEM] = hfn;
        hf = hfn;
        hs = hsn;
    }
    out[(size_t)M_DIM * MEM + idx] = hf;
}

// ---------------------------------------------------------------------------
// Launch
// ---------------------------------------------------------------------------
extern "C" void kernel_launch(void* const* d_in, const int* in_sizes, int n_in,
                              void* d_out, int out_size)
{
    const float* u    = (const float*)d_in[0];   // (128, 512, 512)
    const float* h0   = (const float*)d_in[1];   // (2, 128, 1024)
    const float* W    = (const float*)d_in[2];   // (2048, 512)
    const float* bias = (const float*)d_in[3];   // (2048,)
    float* out = (float*)d_out;

    cudaFuncSetAttribute(gemm_mma_kernel, cudaFuncAttributeMaxDynamicSharedMemorySize, SMEM_TOTAL);

    conv_a_kernel<<<(M_DIM * IN_DIM / 2) / 256, 256>>>(u);   // 65536 blocks
    conv_w_kernel<<<(NOUT * IN_DIM / 2) / 256, 256>>>(W);    // 2048 blocks

    dim3 grid(16, 512);
    gemm_mma_kernel<<<grid, 128, SMEM_TOTAL>>>(bias);

    scan_kernel<<<(B_DIM * MEM) / 256, 256>>>(h0, out);
}

// round 6
// speedup vs baseline: 2.1027x; 1.3430x over previous
#include <cuda_runtime.h>
#include <cuda_fp16.h>
#include <cstdint>
#include <cstddef>

// ---------------------------------------------------------------------------
// Problem dims
// ---------------------------------------------------------------------------
#define B_DIM   128
#define L_DIM   512
#define IN_DIM  512
#define MEM     1024
#define NOUT    2048
#define M_DIM   (B_DIM * L_DIM)      // 65536

#define NCHUNK  16                   // K' = 1024 = 16 * 64  (A*Wh | A*Wl)

// ---------------------------------------------------------------------------
// Device scratch (static allocation — no runtime alloc)
// g_A2: [mt(512)][chunk(8)][128 rows][64 cols] fp16 (single-rounded A),
//       SW128-swizzled 16KB blocks
// g_W2: [wt(16)][chunk(16)][128 rows][64 cols] fp16: chunks 0-7 = Wh, 8-15 = Wl
// ---------------------------------------------------------------------------
__device__ float   g_emb[(size_t)M_DIM * NOUT];     // 512 MB
__device__ __half  g_A2[(size_t)M_DIM * 512];       // 64 MB
__device__ __half  g_W2[(size_t)NOUT * 1024];       // 4 MB

// ---------------------------------------------------------------------------
// Helpers
// ---------------------------------------------------------------------------
__device__ __forceinline__ uint32_t smem_u32(const void* p) {
    uint32_t a;
    asm("{ .reg .u64 t; cvta.to.shared.u64 t, %1; cvt.u32.u64 %0, t; }" : "=r"(a) : "l"(p));
    return a;
}
__device__ __forceinline__ uint32_t swz(uint32_t b) { return b ^ ((b >> 3) & 0x70); }

__device__ __forceinline__ void cp_async16(uint32_t dst, const void* src) {
    asm volatile("cp.async.cg.shared.global [%0], [%1], 16;" :: "r"(dst), "l"(src) : "memory");
}
__device__ __forceinline__ void cp_commit() {
    asm volatile("cp.async.commit_group;" ::: "memory");
}
template <int N>
__device__ __forceinline__ void cp_wait() {
    asm volatile("cp.async.wait_group %0;" :: "n"(N) : "memory");
}

#define LDSM4(r0, r1, r2, r3, a) \
    asm volatile("ldmatrix.sync.aligned.m8n8.x4.shared.b16 {%0,%1,%2,%3}, [%4];" \
                 : "=r"(r0), "=r"(r1), "=r"(r2), "=r"(r3) : "r"(a))

#define MMA16816(c0, c1, c2, c3, a0, a1, a2, a3, b0, b1) \
    asm volatile("mma.sync.aligned.m16n8k16.row.col.f32.f16.f16.f32 " \
                 "{%0,%1,%2,%3}, {%4,%5,%6,%7}, {%8,%9}, {%0,%1,%2,%3};" \
                 : "+f"(c0), "+f"(c1), "+f"(c2), "+f"(c3) \
                 : "r"(a0), "r"(a1), "r"(a2), "r"(a3), "r"(b0), "r"(b1))

// fast tanh (error ~1e-6, correctness threshold is 1e-3)
__device__ __forceinline__ float tanh_fast(float x) {
    float a = fabsf(x);
    float e = __expf(-2.0f * a);
    float r = __fdividef(1.0f - e, 1.0f + e);
    return copysignf(r, x);
}

// ---------------------------------------------------------------------------
// Conversion kernels
// ---------------------------------------------------------------------------
// A: fp32 -> fp16 single-rounded, tiled + SW128 pre-swizzled 16KB blocks.
__global__ __launch_bounds__(256) void conv_a_kernel(const float* __restrict__ u) {
    int idx = blockIdx.x * 256 + threadIdx.x;      // 8,388,608 threads
    int m = idx >> 8;
    int k = (idx & 255) * 2;
    float2 v = *(const float2*)(u + (size_t)m * IN_DIM + k);
    __half h0 = __float2half_rn(v.x);
    __half h1 = __float2half_rn(v.y);
    uint32_t hp = (uint32_t)*(unsigned short*)&h0 | ((uint32_t)*(unsigned short*)&h1 << 16);
    int mt = m >> 7, r = m & 127;
    int ch = k >> 6, c = k & 63;
    uint32_t off = swz((uint32_t)(r * 128 + c * 2));
    char* base = (char*)g_A2;
    *(uint32_t*)(base + (((size_t)(mt * 8 + ch)) << 14) + off) = hp;
}

// W: fp32 -> fp16 hi + fp16 lo residual.
__global__ __launch_bounds__(256) void conv_w_kernel(const float* __restrict__ W) {
    int idx = blockIdx.x * 256 + threadIdx.x;      // 524,288 threads
    int n = idx >> 8;
    int k = (idx & 255) * 2;
    float2 v = *(const float2*)(W + (size_t)n * IN_DIM + k);
    __half h0 = __float2half_rn(v.x);
    __half h1 = __float2half_rn(v.y);
    __half l0 = __float2half_rn(v.x - __half2float(h0));
    __half l1 = __float2half_rn(v.y - __half2float(h1));
    uint32_t hp = (uint32_t)*(unsigned short*)&h0 | ((uint32_t)*(unsigned short*)&h1 << 16);
    uint32_t lp = (uint32_t)*(unsigned short*)&l0 | ((uint32_t)*(unsigned short*)&l1 << 16);
    int nt = n >> 7, r = n & 127;
    int ch = k >> 6, c = k & 63;
    uint32_t off = swz((uint32_t)(r * 128 + c * 2));
    char* base = (char*)g_W2;
    *(uint32_t*)(base + (((size_t)(nt * 16 + ch))     << 14) + off) = hp;
    *(uint32_t*)(base + (((size_t)(nt * 16 + 8 + ch)) << 14) + off) = lp;
}

// ---------------------------------------------------------------------------
// fp16 warp-MMA GEMM: C[m][n] = sum_{k'=0..1023} A'[m][k'] * W'[n][k']
// chunks 0-7:  A(c)   * Wh(c)
// chunks 8-15: A(c-8) * Wl(c-8)
// CTA tile 128x128, BK=64, 128 threads (4 warps, 2(m) x 2(n), warp tile 64x64).
// 3-stage cp.async pipeline, 96 KB smem, 2 CTAs/SM. Grid (16, 512).
// ---------------------------------------------------------------------------
#define NST 3
#define STAGE_BYTES 32768                     // A 16KB + B 16KB
#define SMEM_TOTAL (NST * STAGE_BYTES)        // 96 KB

__global__ __launch_bounds__(128, 2) void gemm_mma_kernel(const float* __restrict__ bias) {
    extern __shared__ __align__(1024) char smem[];
    const uint32_t sm   = smem_u32(smem);
    const int tid  = threadIdx.x;
    const int wid  = tid >> 5;
    const int lane = tid & 31;
    const int nt   = blockIdx.x;     // 0..15
    const int mt   = blockIdx.y;     // 0..511
    const int wm   = wid >> 1;       // 0..1
    const int wn   = wid & 1;        // 0..1

    const char* Ab = (const char*)g_A2 + ((size_t)mt << 17);   // mt * 8 blocks * 16KB
    const char* Bb = (const char*)g_W2 + ((size_t)nt << 18);   // nt * 16 blocks * 16KB

    float acc[4][8][4];
#pragma unroll
    for (int i = 0; i < 4; i++)
#pragma unroll
        for (int j = 0; j < 8; j++)
#pragma unroll
            for (int e = 0; e < 4; e++) acc[i][j][e] = 0.0f;

    // ldmatrix per-lane addressing (SW128): phys = row*128 + ((c16 ^ (row&7))*16)
    const int jj = lane >> 3;        // matrix index 0..3
    const int rl = lane & 7;
    uint32_t arow[4], brow[4];
#pragma unroll
    for (int mi = 0; mi < 4; mi++)
        arow[mi] = (uint32_t)((wm * 64 + mi * 16 + (jj & 1) * 8 + rl) * 128);
#pragma unroll
    for (int p = 0; p < 4; p++)
        brow[p] = (uint32_t)((wn * 64 + p * 16 + (jj & 1) * 8 + rl) * 128);

    auto load_stage = [&](int c, int s) {
        const char* As = Ab + ((size_t)(c & 7) << 14);   // A reused for hi and lo passes
        const char* Bs = Bb + ((size_t)c << 14);         // W: chunks 0-15 = [Wh | Wl]
        uint32_t dst = sm + (uint32_t)s * STAGE_BYTES;
#pragma unroll
        for (int i = 0; i < 8; i++) {
            uint32_t off = (uint32_t)(tid + i * 128) * 16;
            cp_async16(dst + off, As + off);
        }
#pragma unroll
        for (int i = 0; i < 8; i++) {
            uint32_t off = (uint32_t)(tid + i * 128) * 16;
            cp_async16(dst + 16384 + off, Bs + off);
        }
        cp_commit();
    };

    load_stage(0, 0);
    load_stage(1, 1);

    for (int ck = 0; ck < NCHUNK; ck++) {
        const int s = ck % NST;
        cp_wait<1>();
        __syncthreads();
        if (ck + 2 < NCHUNK) load_stage(ck + 2, (ck + 2) % NST);

        const uint32_t sA = sm + (uint32_t)s * STAGE_BYTES;
        const uint32_t sB = sA + 16384;

#pragma unroll
        for (int ks = 0; ks < 4; ks++) {
            const uint32_t cb = (uint32_t)(((2 * ks + (jj >> 1)) ^ rl) * 16);
            uint32_t a[4][4], br[4][4];
#pragma unroll
            for (int mi = 0; mi < 4; mi++)
                LDSM4(a[mi][0], a[mi][1], a[mi][2], a[mi][3], sA + arow[mi] + cb);
#pragma unroll
            for (int p = 0; p < 4; p++)
                LDSM4(br[p][0], br[p][1], br[p][2], br[p][3], sB + brow[p] + cb);
#pragma unroll
            for (int mi = 0; mi < 4; mi++) {
#pragma unroll
                for (int ni = 0; ni < 8; ni++) {
                    const int p = ni >> 1, sub = ni & 1;
                    MMA16816(acc[mi][ni][0], acc[mi][ni][1], acc[mi][ni][2], acc[mi][ni][3],
                             a[mi][0], a[mi][1], a[mi][2], a[mi][3],
                             br[p][sub], br[p][sub + 2]);
                }
            }
        }
    }

    // Epilogue: bias + soma-bias transform on first 1024 cols, streamed fp32 stores
    const int  n0    = nt * 128;
    const bool is_sb = (nt < 8);
#pragma unroll
    for (int mi = 0; mi < 4; mi++) {
        const int row0 = mt * 128 + wm * 64 + mi * 16 + (lane >> 2);
#pragma unroll
        for (int ni = 0; ni < 8; ni++) {
            const int col = n0 + wn * 64 + ni * 8 + (lane & 3) * 2;
            const float2 b2 = *(const float2*)(bias + col);
            float v0 = acc[mi][ni][0] + b2.x;
            float v1 = acc[mi][ni][1] + b2.y;
            float v2 = acc[mi][ni][2] + b2.x;
            float v3 = acc[mi][ni][3] + b2.y;
            if (is_sb) {
                v0 = 5.0f * tanh_fast(v0 * 0.2f);
                v1 = 5.0f * tanh_fast(v1 * 0.2f);
                v2 = 5.0f * tanh_fast(v2 * 0.2f);
                v3 = 5.0f * tanh_fast(v3 * 0.2f);
            }
            __stcs((float2*)&g_emb[(size_t)row0 * NOUT + col],       make_float2(v0, v1));
            __stcs((float2*)&g_emb[(size_t)(row0 + 8) * NOUT + col], make_float2(v2, v3));
        }
    }
}

// ---------------------------------------------------------------------------
// Phase 2: sequential scan over L. One thread per (b, mem) lane.
// out layout: h_t [B][L][MEM] ++ hf_last [B][MEM]
// ---------------------------------------------------------------------------
__global__ __launch_bounds__(256) void scan_kernel(const float* __restrict__ h0,
                                                   float* __restrict__ out)
{
    const int idx = blockIdx.x * 256 + threadIdx.x;
    const int b   = idx >> 10;

    float hf = h0[idx];
    float hs = h0[B_DIM * MEM + idx];

    const float* e = g_emb + (size_t)b * L_DIM * NOUT + (idx & (MEM - 1));
    float*       o = out   + (size_t)b * L_DIM * MEM  + (idx & (MEM - 1));

#pragma unroll 4
    for (int l = 0; l < L_DIM; l++) {
        const float sb = e[(size_t)l * NOUT];
        const float io = e[(size_t)l * NOUT + MEM];

        const float hsb = hs + 0.4f;
        const float x   = io + 4.0f * hf - 7.0f * hsb * hsb + sb;
        const float hfn = tanh_fast(x);
        const float z   = (hf - 0.5f) * 10.0f;
        const float sig = __fdividef(1.0f, 1.0f + __expf(-z));
        const float eps = 0.9f + 0.9f * sig;
        const float hsn = (1.0f - eps) * hs + eps * hf;

        o[(size_t)l * MEM] = hfn;
        hf = hfn;
        hs = hsn;
    }
    out[(size_t)M_DIM * MEM + idx] = hf;
}

// ---------------------------------------------------------------------------
// Launch
// ---------------------------------------------------------------------------
extern "C" void kernel_launch(void* const* d_in, const int* in_sizes, int n_in,
                              void* d_out, int out_size)
{
    const float* u    = (const float*)d_in[0];   // (128, 512, 512)
    const float* h0   = (const float*)d_in[1];   // (2, 128, 1024)
    const float* W    = (const float*)d_in[2];   // (2048, 512)
    const float* bias = (const float*)d_in[3];   // (2048,)
    float* out = (float*)d_out;

    cudaFuncSetAttribute(gemm_mma_kernel, cudaFuncAttributeMaxDynamicSharedMemorySize, SMEM_TOTAL);

    conv_a_kernel<<<(M_DIM * IN_DIM / 2) / 256, 256>>>(u);   // 32768 blocks
    conv_w_kernel<<<(NOUT * IN_DIM / 2) / 256, 256>>>(W);    // 2048 blocks

    dim3 grid(16, 512);
    gemm_mma_kernel<<<grid, 128, SMEM_TOTAL>>>(bias);

    scan_kernel<<<(B_DIM * MEM) / 256, 256>>>(h0, out);
}

// round 7
// speedup vs baseline: 3.1479x; 1.4971x over previous
#include <cuda_runtime.h>
#include <cuda_fp16.h>
#include <cstdint>
#include <cstddef>

// ---------------------------------------------------------------------------
// Problem dims
// ---------------------------------------------------------------------------
#define B_DIM   128
#define L_DIM   512
#define IN_DIM  512
#define MEM     1024
#define NOUT    2048
#define M_DIM   (B_DIM * L_DIM)      // 65536

#define NCHUNK  8                    // K' = 512 = 8 * 64 (single fp16 pass)

// ---------------------------------------------------------------------------
// Device scratch (static allocation — no runtime alloc)
// g_A2: [mt(512)][chunk(8)][128 rows][64 cols] fp16, SW128-swizzled 16KB blocks
// g_W2: [wt(16)][chunk(8)][128 rows][64 cols] fp16, same layout
// ---------------------------------------------------------------------------
__device__ float   g_emb[(size_t)M_DIM * NOUT];     // 512 MB
__device__ __half  g_A2[(size_t)M_DIM * 512];       // 64 MB
__device__ __half  g_W2[(size_t)NOUT * 512];        // 2 MB

// ---------------------------------------------------------------------------
// Helpers
// ---------------------------------------------------------------------------
__device__ __forceinline__ uint32_t smem_u32(const void* p) {
    uint32_t a;
    asm("{ .reg .u64 t; cvta.to.shared.u64 t, %1; cvt.u32.u64 %0, t; }" : "=r"(a) : "l"(p));
    return a;
}
__device__ __forceinline__ uint32_t swz(uint32_t b) { return b ^ ((b >> 3) & 0x70); }

__device__ __forceinline__ void cp_async16(uint32_t dst, const void* src) {
    asm volatile("cp.async.cg.shared.global [%0], [%1], 16;" :: "r"(dst), "l"(src) : "memory");
}
__device__ __forceinline__ void cp_commit() {
    asm volatile("cp.async.commit_group;" ::: "memory");
}
template <int N>
__device__ __forceinline__ void cp_wait() {
    asm volatile("cp.async.wait_group %0;" :: "n"(N) : "memory");
}

#define LDSM4(r0, r1, r2, r3, a) \
    asm volatile("ldmatrix.sync.aligned.m8n8.x4.shared.b16 {%0,%1,%2,%3}, [%4];" \
                 : "=r"(r0), "=r"(r1), "=r"(r2), "=r"(r3) : "r"(a))

#define MMA16816(c0, c1, c2, c3, a0, a1, a2, a3, b0, b1) \
    asm volatile("mma.sync.aligned.m16n8k16.row.col.f32.f16.f16.f32 " \
                 "{%0,%1,%2,%3}, {%4,%5,%6,%7}, {%8,%9}, {%0,%1,%2,%3};" \
                 : "+f"(c0), "+f"(c1), "+f"(c2), "+f"(c3) \
                 : "r"(a0), "r"(a1), "r"(a2), "r"(a3), "r"(b0), "r"(b1))

// fast tanh (error ~1e-6, correctness threshold is 1e-3)
__device__ __forceinline__ float tanh_fast(float x) {
    float a = fabsf(x);
    float e = __expf(-2.0f * a);
    float r = __fdividef(1.0f - e, 1.0f + e);
    return copysignf(r, x);
}

// ---------------------------------------------------------------------------
// Conversion kernels: fp32 -> fp16 single-rounded, tiled + SW128 pre-swizzled
// ---------------------------------------------------------------------------
__global__ __launch_bounds__(256) void conv_a_kernel(const float* __restrict__ u) {
    int idx = blockIdx.x * 256 + threadIdx.x;      // 8,388,608 threads
    int m = idx >> 8;
    int k = (idx & 255) * 2;
    float2 v = *(const float2*)(u + (size_t)m * IN_DIM + k);
    __half h0 = __float2half_rn(v.x);
    __half h1 = __float2half_rn(v.y);
    uint32_t hp = (uint32_t)*(unsigned short*)&h0 | ((uint32_t)*(unsigned short*)&h1 << 16);
    int mt = m >> 7, r = m & 127;
    int ch = k >> 6, c = k & 63;
    uint32_t off = swz((uint32_t)(r * 128 + c * 2));
    char* base = (char*)g_A2;
    *(uint32_t*)(base + (((size_t)(mt * 8 + ch)) << 14) + off) = hp;
}

__global__ __launch_bounds__(256) void conv_w_kernel(const float* __restrict__ W) {
    int idx = blockIdx.x * 256 + threadIdx.x;      // 524,288 threads
    int n = idx >> 8;
    int k = (idx & 255) * 2;
    float2 v = *(const float2*)(W + (size_t)n * IN_DIM + k);
    __half h0 = __float2half_rn(v.x);
    __half h1 = __float2half_rn(v.y);
    uint32_t hp = (uint32_t)*(unsigned short*)&h0 | ((uint32_t)*(unsigned short*)&h1 << 16);
    int nt = n >> 7, r = n & 127;
    int ch = k >> 6, c = k & 63;
    uint32_t off = swz((uint32_t)(r * 128 + c * 2));
    char* base = (char*)g_W2;
    *(uint32_t*)(base + (((size_t)(nt * 8 + ch)) << 14) + off) = hp;
}

// ---------------------------------------------------------------------------
// fp16 warp-MMA GEMM: C[m][n] = sum_{k=0..511} A'[m][k] * W'[n][k]
// CTA tile 128x128, BK=64, 128 threads (4 warps, 2(m) x 2(n), warp tile 64x64).
// 3-stage cp.async pipeline, 96 KB smem, 2 CTAs/SM. Grid (16, 512).
// ---------------------------------------------------------------------------
#define NST 3
#define STAGE_BYTES 32768                     // A 16KB + B 16KB
#define SMEM_TOTAL (NST * STAGE_BYTES)        // 96 KB

__global__ __launch_bounds__(128, 2) void gemm_mma_kernel(const float* __restrict__ bias) {
    extern __shared__ __align__(1024) char smem[];
    const uint32_t sm   = smem_u32(smem);
    const int tid  = threadIdx.x;
    const int wid  = tid >> 5;
    const int lane = tid & 31;
    const int nt   = blockIdx.x;     // 0..15
    const int mt   = blockIdx.y;     // 0..511
    const int wm   = wid >> 1;       // 0..1
    const int wn   = wid & 1;        // 0..1

    const char* Ab = (const char*)g_A2 + ((size_t)mt << 17);   // mt * 8 blocks * 16KB
    const char* Bb = (const char*)g_W2 + ((size_t)nt << 17);   // nt * 8 blocks * 16KB

    float acc[4][8][4];
#pragma unroll
    for (int i = 0; i < 4; i++)
#pragma unroll
        for (int j = 0; j < 8; j++)
#pragma unroll
            for (int e = 0; e < 4; e++) acc[i][j][e] = 0.0f;

    // ldmatrix per-lane addressing (SW128): phys = row*128 + ((c16 ^ (row&7))*16)
    const int jj = lane >> 3;        // matrix index 0..3
    const int rl = lane & 7;
    uint32_t arow[4], brow[4];
#pragma unroll
    for (int mi = 0; mi < 4; mi++)
        arow[mi] = (uint32_t)((wm * 64 + mi * 16 + (jj & 1) * 8 + rl) * 128);
#pragma unroll
    for (int p = 0; p < 4; p++)
        brow[p] = (uint32_t)((wn * 64 + p * 16 + (jj & 1) * 8 + rl) * 128);

    auto load_stage = [&](int c, int s) {
        const char* As = Ab + ((size_t)c << 14);
        const char* Bs = Bb + ((size_t)c << 14);
        uint32_t dst = sm + (uint32_t)s * STAGE_BYTES;
#pragma unroll
        for (int i = 0; i < 8; i++) {
            uint32_t off = (uint32_t)(tid + i * 128) * 16;
            cp_async16(dst + off, As + off);
        }
#pragma unroll
        for (int i = 0; i < 8; i++) {
            uint32_t off = (uint32_t)(tid + i * 128) * 16;
            cp_async16(dst + 16384 + off, Bs + off);
        }
        cp_commit();
    };

    load_stage(0, 0);
    load_stage(1, 1);

    for (int ck = 0; ck < NCHUNK; ck++) {
        const int s = ck % NST;
        cp_wait<1>();
        __syncthreads();
        if (ck + 2 < NCHUNK) load_stage(ck + 2, (ck + 2) % NST);

        const uint32_t sA = sm + (uint32_t)s * STAGE_BYTES;
        const uint32_t sB = sA + 16384;

#pragma unroll
        for (int ks = 0; ks < 4; ks++) {
            const uint32_t cb = (uint32_t)(((2 * ks + (jj >> 1)) ^ rl) * 16);
            uint32_t a[4][4], br[4][4];
#pragma unroll
            for (int mi = 0; mi < 4; mi++)
                LDSM4(a[mi][0], a[mi][1], a[mi][2], a[mi][3], sA + arow[mi] + cb);
#pragma unroll
            for (int p = 0; p < 4; p++)
                LDSM4(br[p][0], br[p][1], br[p][2], br[p][3], sB + brow[p] + cb);
#pragma unroll
            for (int mi = 0; mi < 4; mi++) {
#pragma unroll
                for (int ni = 0; ni < 8; ni++) {
                    const int p = ni >> 1, sub = ni & 1;
                    MMA16816(acc[mi][ni][0], acc[mi][ni][1], acc[mi][ni][2], acc[mi][ni][3],
                             a[mi][0], a[mi][1], a[mi][2], a[mi][3],
                             br[p][sub], br[p][sub + 2]);
                }
            }
        }
    }

    // Epilogue: bias + soma-bias transform on first 1024 cols, streamed fp32 stores
    const int  n0    = nt * 128;
    const bool is_sb = (nt < 8);
#pragma unroll
    for (int mi = 0; mi < 4; mi++) {
        const int row0 = mt * 128 + wm * 64 + mi * 16 + (lane >> 2);
#pragma unroll
        for (int ni = 0; ni < 8; ni++) {
            const int col = n0 + wn * 64 + ni * 8 + (lane & 3) * 2;
            const float2 b2 = *(const float2*)(bias + col);
            float v0 = acc[mi][ni][0] + b2.x;
            float v1 = acc[mi][ni][1] + b2.y;
            float v2 = acc[mi][ni][2] + b2.x;
            float v3 = acc[mi][ni][3] + b2.y;
            if (is_sb) {
                v0 = 5.0f * tanh_fast(v0 * 0.2f);
                v1 = 5.0f * tanh_fast(v1 * 0.2f);
                v2 = 5.0f * tanh_fast(v2 * 0.2f);
                v3 = 5.0f * tanh_fast(v3 * 0.2f);
            }
            __stcs((float2*)&g_emb[(size_t)row0 * NOUT + col],       make_float2(v0, v1));
            __stcs((float2*)&g_emb[(size_t)(row0 + 8) * NOUT + col], make_float2(v2, v3));
        }
    }
}

// ---------------------------------------------------------------------------
// Phase 2: sequential scan over L. One thread per (b, mem) lane.
// out layout: h_t [B][L][MEM] ++ hf_last [B][MEM]
// ---------------------------------------------------------------------------
__global__ __launch_bounds__(256) void scan_kernel(const float* __restrict__ h0,
                                                   float* __restrict__ out)
{
    const int idx = blockIdx.x * 256 + threadIdx.x;
    const int b   = idx >> 10;

    float hf = h0[idx];
    float hs = h0[B_DIM * MEM + idx];

    const float* e = g_emb + (size_t)b * L_DIM * NOUT + (idx & (MEM - 1));
    float*       o = out   + (size_t)b * L_DIM * MEM  + (idx & (MEM - 1));

#pragma unroll 4
    for (int l = 0; l < L_DIM; l++) {
        const float sb = e[(size_t)l * NOUT];
        const float io = e[(size_t)l * NOUT + MEM];

        const float hsb = hs + 0.4f;
        const float x   = io + 4.0f * hf - 7.0f * hsb * hsb + sb;
        const float hfn = tanh_fast(x);
        const float z   = (hf - 0.5f) * 10.0f;
        const float sig = __fdividef(1.0f, 1.0f + __expf(-z));
        const float eps = 0.9f + 0.9f * sig;
        const float hsn = (1.0f - eps) * hs + eps * hf;

        o[(size_t)l * MEM] = hfn;
        hf = hfn;
        hs = hsn;
    }
    out[(size_t)M_DIM * MEM + idx] = hf;
}

// ---------------------------------------------------------------------------
// Launch
// ---------------------------------------------------------------------------
extern "C" void kernel_launch(void* const* d_in, const int* in_sizes, int n_in,
                              void* d_out, int out_size)
{
    const float* u    = (const float*)d_in[0];   // (128, 512, 512)
    const float* h0   = (const float*)d_in[1];   // (2, 128, 1024)
    const float* W    = (const float*)d_in[2];   // (2048, 512)
    const float* bias = (const float*)d_in[3];   // (2048,)
    float* out = (float*)d_out;

    cudaFuncSetAttribute(gemm_mma_kernel, cudaFuncAttributeMaxDynamicSharedMemorySize, SMEM_TOTAL);

    conv_a_kernel<<<(M_DIM * IN_DIM / 2) / 256, 256>>>(u);   // 32768 blocks
    conv_w_kernel<<<(NOUT * IN_DIM / 2) / 256, 256>>>(W);    // 2048 blocks

    dim3 grid(16, 512);
    gemm_mma_kernel<<<grid, 128, SMEM_TOTAL>>>(bias);

    scan_kernel<<<(B_DIM * MEM) / 256, 256>>>(h0, out);
}